// round 2
// baseline (speedup 1.0000x reference)
#include <cuda_runtime.h>
#include <cuda_bf16.h>
#include <math.h>

// ---------------- problem constants ----------------
#define BATCH 32
#define HH 56
#define WW 56
#define CDIM 384
#define NHEADS 12
#define HDIM 32
#define WSZ 7
#define NTOK 49          // 7*7
#define NWIN 64          // (56/7)^2
#define BN 2048          // BATCH*NWIN
#define ROWS 100352      // BATCH*HH*WW == BN*NTOK
#define HID 1536
#define QKVN 1152

// ---------------- scratch (no allocation allowed) ----------------
__device__ float g_win[(size_t)ROWS * CDIM];     // LN1 + shift + partition output / LN2 output
__device__ float g_qkv[(size_t)ROWS * QKVN];     // qkv activations
__device__ float g_att[(size_t)ROWS * CDIM];     // attention output (window layout)
__device__ float g_hid[(size_t)ROWS * HID];      // mlp hidden

// ---------------- LN1 + cyclic shift + window partition ----------------
__global__ void ln1_part_kernel(const float* __restrict__ x,
                                const float* __restrict__ g,
                                const float* __restrict__ b,
                                float* __restrict__ out) {
    int row = blockIdx.x;                 // row in x: (b, hh, ww)
    int tid = threadIdx.x;                // 128 threads, 3 elems each
    const float* xr = x + (size_t)row * CDIM;
    float v0 = xr[tid], v1 = xr[tid + 128], v2 = xr[tid + 256];
    float s = v0 + v1 + v2;
    float sq = v0 * v0 + v1 * v1 + v2 * v2;
#pragma unroll
    for (int o = 16; o; o >>= 1) {
        s += __shfl_down_sync(0xffffffffu, s, o);
        sq += __shfl_down_sync(0xffffffffu, sq, o);
    }
    __shared__ float rs[4], rq[4];
    int w = tid >> 5, l = tid & 31;
    if (l == 0) { rs[w] = s; rq[w] = sq; }
    __syncthreads();
    float ts = rs[0] + rs[1] + rs[2] + rs[3];
    float tq = rq[0] + rq[1] + rq[2] + rq[3];
    float mean = ts * (1.0f / CDIM);
    float var = tq * (1.0f / CDIM) - mean * mean;
    float rstd = rsqrtf(var + 1e-5f);

    // destination: roll(-3,-3) then partition into windows
    int bb = row / (HH * WW);
    int rem = row - bb * (HH * WW);
    int hh = rem / WW, ww = rem - (rem / WW) * WW;
    int i = (hh >= 3) ? hh - 3 : hh + 53;
    int j = (ww >= 3) ? ww - 3 : ww + 53;
    int widx = (i / WSZ) * 8 + (j / WSZ);
    int tok = (i % WSZ) * WSZ + (j % WSZ);
    size_t drow = ((size_t)(bb * NWIN + widx) * NTOK + tok) * CDIM;
    out[drow + tid]       = (v0 - mean) * rstd * g[tid]       + b[tid];
    out[drow + tid + 128] = (v1 - mean) * rstd * g[tid + 128] + b[tid + 128];
    out[drow + tid + 256] = (v2 - mean) * rstd * g[tid + 256] + b[tid + 256];
}

// ---------------- LN2 (plain, row->row) ----------------
__global__ void ln2_kernel(const float* __restrict__ x,
                           const float* __restrict__ g,
                           const float* __restrict__ b,
                           float* __restrict__ out) {
    int row = blockIdx.x;
    int tid = threadIdx.x;
    const float* xr = x + (size_t)row * CDIM;
    float v0 = xr[tid], v1 = xr[tid + 128], v2 = xr[tid + 256];
    float s = v0 + v1 + v2;
    float sq = v0 * v0 + v1 * v1 + v2 * v2;
#pragma unroll
    for (int o = 16; o; o >>= 1) {
        s += __shfl_down_sync(0xffffffffu, s, o);
        sq += __shfl_down_sync(0xffffffffu, sq, o);
    }
    __shared__ float rs[4], rq[4];
    int w = tid >> 5, l = tid & 31;
    if (l == 0) { rs[w] = s; rq[w] = sq; }
    __syncthreads();
    float ts = rs[0] + rs[1] + rs[2] + rs[3];
    float tq = rq[0] + rq[1] + rq[2] + rq[3];
    float mean = ts * (1.0f / CDIM);
    float var = tq * (1.0f / CDIM) - mean * mean;
    float rstd = rsqrtf(var + 1e-5f);
    size_t o0 = (size_t)row * CDIM;
    out[o0 + tid]       = (v0 - mean) * rstd * g[tid]       + b[tid];
    out[o0 + tid + 128] = (v1 - mean) * rstd * g[tid + 128] + b[tid + 128];
    out[o0 + tid + 256] = (v2 - mean) * rstd * g[tid + 256] + b[tid + 256];
}

// ---------------- generic 128x128x8 SGEMM with epilogues ----------------
// EPI: 0 = bias + store
//      1 = bias + window-reverse scatter + residual add (proj)
//      2 = bias + exact GELU
//      3 = bias + accumulate into C (fc2: C += val)
template <int EPI>
__global__ __launch_bounds__(256)
void gemm128(const float* __restrict__ A, const float* __restrict__ Bm,
             const float* __restrict__ bias, float* __restrict__ Cout,
             int M, int Nm, int K, const float* __restrict__ resid) {
    __shared__ float As[8][128];
    __shared__ float Bs[8][128];
    int tid = threadIdx.x;
    int row0 = blockIdx.y * 128;
    int col0 = blockIdx.x * 128;

    int arow = tid >> 1;            // 0..127
    int ak   = (tid & 1) * 4;       // 0 or 4
    int bk   = tid >> 5;            // 0..7
    int bj   = (tid & 31) * 4;      // 0..124

    const float* Aptr = A + (size_t)(row0 + arow) * K + ak;
    const float* Bptr = Bm + (size_t)bk * Nm + col0 + bj;

    int tx = tid & 15, ty = tid >> 4;
    float acc[8][8];
#pragma unroll
    for (int i = 0; i < 8; i++)
#pragma unroll
        for (int j = 0; j < 8; j++) acc[i][j] = 0.0f;

    for (int k0 = 0; k0 < K; k0 += 8) {
        float4 av = *(const float4*)(Aptr + k0);
        float4 bv = *(const float4*)(Bptr + (size_t)k0 * Nm);
        As[ak + 0][arow] = av.x;
        As[ak + 1][arow] = av.y;
        As[ak + 2][arow] = av.z;
        As[ak + 3][arow] = av.w;
        *(float4*)&Bs[bk][bj] = bv;
        __syncthreads();
#pragma unroll
        for (int kk = 0; kk < 8; kk++) {
            float a[8], bb[8];
            *(float4*)(a)     = *(const float4*)&As[kk][ty * 8];
            *(float4*)(a + 4) = *(const float4*)&As[kk][ty * 8 + 4];
            *(float4*)(bb)     = *(const float4*)&Bs[kk][tx * 8];
            *(float4*)(bb + 4) = *(const float4*)&Bs[kk][tx * 8 + 4];
#pragma unroll
            for (int i = 0; i < 8; i++)
#pragma unroll
                for (int j = 0; j < 8; j++) acc[i][j] += a[i] * bb[j];
        }
        __syncthreads();
    }

    float bval[8];
#pragma unroll
    for (int j = 0; j < 8; j++) bval[j] = bias[col0 + tx * 8 + j];

#pragma unroll
    for (int i = 0; i < 8; i++) {
        int r = row0 + ty * 8 + i;
        if (EPI == 1) {
            // r = bn*49 + tok ; window reverse + roll(+3,+3) + residual
            int bn = r / NTOK, tok = r - (r / NTOK) * NTOK;
            int bbat = bn >> 6, w = bn & 63;
            int ii = (w >> 3) * WSZ + tok / WSZ;
            int jj = (w & 7) * WSZ + tok % WSZ;
            int hh = (ii < 53) ? ii + 3 : ii - 53;
            int ww = (jj < 53) ? jj + 3 : jj - 53;
            size_t xrow = ((size_t)bbat * (HH * WW) + hh * WW + ww) * CDIM;
#pragma unroll
            for (int j = 0; j < 8; j++) {
                int cidx = col0 + tx * 8 + j;
                Cout[xrow + cidx] = resid[xrow + cidx] + acc[i][j] + bval[j];
            }
        } else {
            size_t off = (size_t)r * Nm + col0 + tx * 8;
#pragma unroll
            for (int jq = 0; jq < 2; jq++) {
                float4 v;
                float t0 = acc[i][jq * 4 + 0] + bval[jq * 4 + 0];
                float t1 = acc[i][jq * 4 + 1] + bval[jq * 4 + 1];
                float t2 = acc[i][jq * 4 + 2] + bval[jq * 4 + 2];
                float t3 = acc[i][jq * 4 + 3] + bval[jq * 4 + 3];
                if (EPI == 2) {
                    t0 = 0.5f * t0 * (1.0f + erff(t0 * 0.70710678118654752f));
                    t1 = 0.5f * t1 * (1.0f + erff(t1 * 0.70710678118654752f));
                    t2 = 0.5f * t2 * (1.0f + erff(t2 * 0.70710678118654752f));
                    t3 = 0.5f * t3 * (1.0f + erff(t3 * 0.70710678118654752f));
                }
                if (EPI == 3) {
                    float* dst = &Cout[off + jq * 4];
                    dst[0] += t0; dst[1] += t1; dst[2] += t2; dst[3] += t3;
                } else {
                    v.x = t0; v.y = t1; v.z = t2; v.w = t3;
                    *(float4*)&Cout[off + jq * 4] = v;
                }
            }
        }
    }
}

// ---------------- attention: one block per (window, head) ----------------
__global__ __launch_bounds__(128)
void attn_kernel(const float* __restrict__ qkv, const float* __restrict__ rpb,
                 const float* __restrict__ mask, float* __restrict__ out) {
    int bn = blockIdx.x;
    int h = blockIdx.y;
    __shared__ float qs[NTOK][33];
    __shared__ float ks[NTOK][33];
    __shared__ float vs[NTOK][32];
    __shared__ float sc[NTOK][50];
    int tid = threadIdx.x;

    size_t base = (size_t)bn * NTOK * QKVN + h * HDIM;
    for (int idx = tid; idx < NTOK * HDIM; idx += 128) {
        int i = idx >> 5, d = idx & 31;
        size_t o = base + (size_t)i * QKVN + d;
        qs[i][d] = qkv[o] * 0.17677669529663687f;   // 1/sqrt(32)
        ks[i][d] = qkv[o + CDIM];
        vs[i][d] = qkv[o + 2 * CDIM];
    }
    __syncthreads();

    const float* mrow = mask + (size_t)(bn & 63) * (NTOK * NTOK);
    for (int t = tid; t < NTOK * NTOK; t += 128) {
        int i = t / NTOK, j = t - (t / NTOK) * NTOK;
        float s = 0.0f;
#pragma unroll
        for (int d = 0; d < HDIM; d++) s += qs[i][d] * ks[j][d];
        int yi = i / WSZ, xi = i % WSZ, yj = j / WSZ, xj = j % WSZ;
        s += rpb[((yi - yj + 6) * 13 + (xi - xj + 6)) * NHEADS + h];
        s += mrow[t];
        sc[i][j] = s;
    }
    __syncthreads();

    if (tid < NTOK) {
        float m = -1e30f;
#pragma unroll
        for (int j = 0; j < NTOK; j++) m = fmaxf(m, sc[tid][j]);
        float sum = 0.0f;
#pragma unroll
        for (int j = 0; j < NTOK; j++) {
            float e = __expf(sc[tid][j] - m);
            sc[tid][j] = e;
            sum += e;
        }
        float inv = 1.0f / sum;
#pragma unroll
        for (int j = 0; j < NTOK; j++) sc[tid][j] *= inv;
    }
    __syncthreads();

    for (int t = tid; t < NTOK * HDIM; t += 128) {
        int i = t >> 5, d = t & 31;
        float s = 0.0f;
#pragma unroll
        for (int j = 0; j < NTOK; j++) s += sc[i][j] * vs[j][d];
        out[((size_t)bn * NTOK + i) * CDIM + h * HDIM + d] = s;
    }
}

// ---------------- launch ----------------
extern "C" void kernel_launch(void* const* d_in, const int* in_sizes, int n_in,
                              void* d_out, int out_size) {
    const float* x        = (const float*)d_in[0];
    const float* attnmask = (const float*)d_in[1];
    const float* n1g      = (const float*)d_in[2];
    const float* n1b      = (const float*)d_in[3];
    const float* qkv_w    = (const float*)d_in[4];
    const float* qkv_b    = (const float*)d_in[5];
    const float* rpb      = (const float*)d_in[6];
    const float* proj_w   = (const float*)d_in[7];
    const float* proj_b   = (const float*)d_in[8];
    const float* n2g      = (const float*)d_in[9];
    const float* n2b      = (const float*)d_in[10];
    const float* fc1_w    = (const float*)d_in[11];
    const float* fc1_b    = (const float*)d_in[12];
    const float* fc2_w    = (const float*)d_in[13];
    const float* fc2_b    = (const float*)d_in[14];
    float* out = (float*)d_out;

    float *p_win, *p_qkv, *p_att, *p_hid;
    cudaGetSymbolAddress((void**)&p_win, g_win);
    cudaGetSymbolAddress((void**)&p_qkv, g_qkv);
    cudaGetSymbolAddress((void**)&p_att, g_att);
    cudaGetSymbolAddress((void**)&p_hid, g_hid);

    // 1. LN1 + shift + window partition
    ln1_part_kernel<<<ROWS, 128>>>(x, n1g, n1b, p_win);

    // 2. QKV GEMM: [ROWS,384] @ [384,1152]
    gemm128<0><<<dim3(QKVN / 128, ROWS / 128), 256>>>(p_win, qkv_w, qkv_b, p_qkv,
                                                      ROWS, QKVN, CDIM, nullptr);

    // 3. windowed attention
    attn_kernel<<<dim3(BN, NHEADS), 128>>>(p_qkv, rpb, attnmask, p_att);

    // 4. proj GEMM + window reverse + residual  -> d_out holds x_after_attn
    gemm128<1><<<dim3(CDIM / 128, ROWS / 128), 256>>>(p_att, proj_w, proj_b, out,
                                                      ROWS, CDIM, CDIM, x);

    // 5. LN2
    ln2_kernel<<<ROWS, 128>>>(out, n2g, n2b, p_win);

    // 6. fc1 + GELU
    gemm128<2><<<dim3(HID / 128, ROWS / 128), 256>>>(p_win, fc1_w, fc1_b, p_hid,
                                                     ROWS, HID, CDIM, nullptr);

    // 7. fc2 + residual accumulate into d_out
    gemm128<3><<<dim3(CDIM / 128, ROWS / 128), 256>>>(p_hid, fc2_w, fc2_b, out,
                                                      ROWS, CDIM, HID, nullptr);
}

// round 6
// speedup vs baseline: 1.6246x; 1.6246x over previous
#include <cuda_runtime.h>
#include <cuda_bf16.h>
#include <cstdint>
#include <math.h>

// ---------------- problem constants ----------------
#define BATCH 32
#define HH 56
#define WW 56
#define CDIM 384
#define NHEADS 12
#define HDIM 32
#define WSZ 7
#define NTOK 49
#define NWIN 64
#define BN 2048
#define ROWS 100352
#define HID 1536
#define QKVN 1152

// ---------------- scratch ----------------
__device__ float g_win[(size_t)ROWS * CDIM];
__device__ float g_qkv[(size_t)ROWS * QKVN];
__device__ float g_att[(size_t)ROWS * CDIM];
__device__ float g_hid[(size_t)ROWS * HID];
__device__ float g_qkvT[(size_t)QKVN * CDIM];
__device__ float g_projT[(size_t)CDIM * CDIM];
__device__ float g_fc1T[(size_t)HID * CDIM];
__device__ float g_fc2T[(size_t)CDIM * HID];

// ---------------- helpers ----------------
__device__ __forceinline__ uint32_t f2tf(float x) {
    uint32_t r;
    asm("cvt.rna.tf32.f32 %0, %1;" : "=r"(r) : "f"(x));
    return r;
}
__device__ __forceinline__ void mma_tf32(float* c, const uint32_t* a, const uint32_t* b) {
    asm volatile(
        "mma.sync.aligned.m16n8k8.row.col.f32.tf32.tf32.f32 "
        "{%0,%1,%2,%3}, {%4,%5,%6,%7}, {%8,%9}, {%0,%1,%2,%3};"
        : "+f"(c[0]), "+f"(c[1]), "+f"(c[2]), "+f"(c[3])
        : "r"(a[0]), "r"(a[1]), "r"(a[2]), "r"(a[3]), "r"(b[0]), "r"(b[1]));
}

// ======================= tf32 mma.sync GEMM =======================
// Block 128x128, 8 warps (2m x 4n), warp tile 64x32, BK=32, double-buffered.
// A: [M,K] row-major. Bt: [N,K] row-major (== K x N col-major for mma "col").
// smem tiles: 128 rows x 32 k, padded row stride 36 floats.
#define TSTRIDE 36
#define TILEF (128 * TSTRIDE)          // floats per tile
#define GSMEM_BYTES (4 * TILEF * 4)    // A0 A1 B0 B1

// EPI: 0 bias+store | 1 bias+scatter+residual | 2 bias+GELU | 3 bias+accumulate
template <int EPI>
__global__ void __launch_bounds__(256)
mma_gemm(const float* __restrict__ A, const float* __restrict__ Bt,
         const float* __restrict__ bias, float* __restrict__ C,
         int K, int Nm, const float* __restrict__ resid) {
    extern __shared__ uint32_t smem[];
    uint32_t* Asm[2] = {smem, smem + TILEF};
    uint32_t* Bsm[2] = {smem + 2 * TILEF, smem + 3 * TILEF};

    int tid = threadIdx.x;
    int lane = tid & 31, wid = tid >> 5;
    int wm = wid & 1, wn = wid >> 1;            // warp tile: rows wm*64, cols wn*32
    int row0 = blockIdx.y * 128, col0 = blockIdx.x * 128;

    const float* Ab = A + (size_t)row0 * K;
    const float* Bb = Bt + (size_t)col0 * K;

    float acc[4][4][4];
#pragma unroll
    for (int i = 0; i < 4; i++)
#pragma unroll
        for (int j = 0; j < 4; j++)
#pragma unroll
            for (int e = 0; e < 4; e++) acc[i][j][e] = 0.0f;

    // loader: 1024 float4 per tile pair half; f = tid + i*256 -> r=f>>3, c=(f&7)*4
    int lr = tid >> 3, lc = (tid & 7) * 4;

    float4 pa[4], pb[4];
    int nk = K >> 5;

    // prologue: load tile 0
#pragma unroll
    for (int i = 0; i < 4; i++) {
        int r = lr + i * 32;
        pa[i] = *(const float4*)(Ab + (size_t)r * K + lc);
        pb[i] = *(const float4*)(Bb + (size_t)r * K + lc);
    }
#pragma unroll
    for (int i = 0; i < 4; i++) {
        int r = lr + i * 32;
        uint32_t* da = &Asm[0][r * TSTRIDE + lc];
        uint32_t* db = &Bsm[0][r * TSTRIDE + lc];
        da[0] = f2tf(pa[i].x); da[1] = f2tf(pa[i].y); da[2] = f2tf(pa[i].z); da[3] = f2tf(pa[i].w);
        db[0] = f2tf(pb[i].x); db[1] = f2tf(pb[i].y); db[2] = f2tf(pb[i].z); db[3] = f2tf(pb[i].w);
    }
    __syncthreads();

    for (int it = 0; it < nk; ++it) {
        int s = it & 1;
        if (it + 1 < nk) {
            int k0 = (it + 1) << 5;
#pragma unroll
            for (int i = 0; i < 4; i++) {
                int r = lr + i * 32;
                pa[i] = *(const float4*)(Ab + (size_t)r * K + k0 + lc);
                pb[i] = *(const float4*)(Bb + (size_t)r * K + k0 + lc);
            }
        }
        // compute on stage s
        const uint32_t* As = Asm[s];
        const uint32_t* Bs = Bsm[s];
#pragma unroll
        for (int kk = 0; kk < 32; kk += 8) {
            uint32_t af[4][4], bf[4][2];
#pragma unroll
            for (int mf = 0; mf < 4; mf++) {
                const uint32_t* ap = As + (wm * 64 + mf * 16 + (lane >> 2)) * TSTRIDE + kk + (lane & 3);
                af[mf][0] = ap[0];
                af[mf][1] = ap[8 * TSTRIDE];
                af[mf][2] = ap[4];
                af[mf][3] = ap[8 * TSTRIDE + 4];
            }
#pragma unroll
            for (int nf = 0; nf < 4; nf++) {
                const uint32_t* bp = Bs + (wn * 32 + nf * 8 + (lane >> 2)) * TSTRIDE + kk + (lane & 3);
                bf[nf][0] = bp[0];
                bf[nf][1] = bp[4];
            }
#pragma unroll
            for (int mf = 0; mf < 4; mf++)
#pragma unroll
                for (int nf = 0; nf < 4; nf++)
                    mma_tf32(acc[mf][nf], af[mf], bf[nf]);
        }
        if (it + 1 < nk) {
            int s2 = (it + 1) & 1;
#pragma unroll
            for (int i = 0; i < 4; i++) {
                int r = lr + i * 32;
                uint32_t* da = &Asm[s2][r * TSTRIDE + lc];
                uint32_t* db = &Bsm[s2][r * TSTRIDE + lc];
                da[0] = f2tf(pa[i].x); da[1] = f2tf(pa[i].y); da[2] = f2tf(pa[i].z); da[3] = f2tf(pa[i].w);
                db[0] = f2tf(pb[i].x); db[1] = f2tf(pb[i].y); db[2] = f2tf(pb[i].z); db[3] = f2tf(pb[i].w);
            }
        }
        __syncthreads();
    }

    // ---------------- epilogue ----------------
    const float is2 = 0.70710678118654752f;
#pragma unroll
    for (int mf = 0; mf < 4; mf++) {
#pragma unroll
        for (int h = 0; h < 2; h++) {
            int row = row0 + wm * 64 + mf * 16 + (lane >> 2) + h * 8;
            size_t base;
            if (EPI == 1) {
                int bn = row / NTOK, tok = row - bn * NTOK;
                int bbat = bn >> 6, w = bn & 63;
                int ii = (w >> 3) * WSZ + tok / WSZ;
                int jj = (w & 7) * WSZ + tok % WSZ;
                int hh = (ii < 53) ? ii + 3 : ii - 53;
                int ww2 = (jj < 53) ? jj + 3 : jj - 53;
                base = ((size_t)bbat * (HH * WW) + hh * WW + ww2) * CDIM;
            } else {
                base = (size_t)row * Nm;
            }
#pragma unroll
            for (int nf = 0; nf < 4; nf++) {
                int col = col0 + wn * 32 + nf * 8 + (lane & 3) * 2;
                float v0 = acc[mf][nf][h * 2 + 0] + bias[col];
                float v1 = acc[mf][nf][h * 2 + 1] + bias[col + 1];
                if (EPI == 2) {
                    v0 = 0.5f * v0 * (1.0f + erff(v0 * is2));
                    v1 = 0.5f * v1 * (1.0f + erff(v1 * is2));
                }
                size_t off = base + col;
                if (EPI == 1) {
                    float2 rr = *(const float2*)(resid + off);
                    float2 o; o.x = v0 + rr.x; o.y = v1 + rr.y;
                    *(float2*)(C + off) = o;
                } else if (EPI == 3) {
                    float2 o = *(float2*)(C + off);
                    o.x += v0; o.y += v1;
                    *(float2*)(C + off) = o;
                } else {
                    float2 o; o.x = v0; o.y = v1;
                    *(float2*)(C + off) = o;
                }
            }
        }
    }
}

// ---------------- weight transpose [K,N] -> [N,K] ----------------
__global__ void transpose_k(const float* __restrict__ W, float* __restrict__ Wt,
                            int K, int N) {
    __shared__ float t[32][33];
    int k0 = blockIdx.y * 32, n0 = blockIdx.x * 32;
    int x = threadIdx.x, y = threadIdx.y;
    for (int i = y; i < 32; i += 8) t[i][x] = W[(size_t)(k0 + i) * N + n0 + x];
    __syncthreads();
    for (int i = y; i < 32; i += 8) Wt[(size_t)(n0 + i) * K + k0 + x] = t[x][i];
}

// ---------------- LN1 + cyclic shift + window partition ----------------
__global__ void ln1_part_kernel(const float* __restrict__ x,
                                const float* __restrict__ g,
                                const float* __restrict__ b,
                                float* __restrict__ out) {
    int row = blockIdx.x;
    int tid = threadIdx.x;
    const float* xr = x + (size_t)row * CDIM;
    float v0 = xr[tid], v1 = xr[tid + 128], v2 = xr[tid + 256];
    float s = v0 + v1 + v2;
    float sq = v0 * v0 + v1 * v1 + v2 * v2;
#pragma unroll
    for (int o = 16; o; o >>= 1) {
        s += __shfl_down_sync(0xffffffffu, s, o);
        sq += __shfl_down_sync(0xffffffffu, sq, o);
    }
    __shared__ float rs[4], rq[4];
    int w = tid >> 5, l = tid & 31;
    if (l == 0) { rs[w] = s; rq[w] = sq; }
    __syncthreads();
    float ts = rs[0] + rs[1] + rs[2] + rs[3];
    float tq = rq[0] + rq[1] + rq[2] + rq[3];
    float mean = ts * (1.0f / CDIM);
    float var = tq * (1.0f / CDIM) - mean * mean;
    float rstd = rsqrtf(var + 1e-5f);

    int bb = row / (HH * WW);
    int rem = row - bb * (HH * WW);
    int hh = rem / WW, ww = rem - (rem / WW) * WW;
    int i = (hh >= 3) ? hh - 3 : hh + 53;
    int j = (ww >= 3) ? ww - 3 : ww + 53;
    int widx = (i / WSZ) * 8 + (j / WSZ);
    int tok = (i % WSZ) * WSZ + (j % WSZ);
    size_t drow = ((size_t)(bb * NWIN + widx) * NTOK + tok) * CDIM;
    out[drow + tid]       = (v0 - mean) * rstd * g[tid]       + b[tid];
    out[drow + tid + 128] = (v1 - mean) * rstd * g[tid + 128] + b[tid + 128];
    out[drow + tid + 256] = (v2 - mean) * rstd * g[tid + 256] + b[tid + 256];
}

// ---------------- LN2 ----------------
__global__ void ln2_kernel(const float* __restrict__ x,
                           const float* __restrict__ g,
                           const float* __restrict__ b,
                           float* __restrict__ out) {
    int row = blockIdx.x;
    int tid = threadIdx.x;
    const float* xr = x + (size_t)row * CDIM;
    float v0 = xr[tid], v1 = xr[tid + 128], v2 = xr[tid + 256];
    float s = v0 + v1 + v2;
    float sq = v0 * v0 + v1 * v1 + v2 * v2;
#pragma unroll
    for (int o = 16; o; o >>= 1) {
        s += __shfl_down_sync(0xffffffffu, s, o);
        sq += __shfl_down_sync(0xffffffffu, sq, o);
    }
    __shared__ float rs[4], rq[4];
    int w = tid >> 5, l = tid & 31;
    if (l == 0) { rs[w] = s; rq[w] = sq; }
    __syncthreads();
    float ts = rs[0] + rs[1] + rs[2] + rs[3];
    float tq = rq[0] + rq[1] + rq[2] + rq[3];
    float mean = ts * (1.0f / CDIM);
    float var = tq * (1.0f / CDIM) - mean * mean;
    float rstd = rsqrtf(var + 1e-5f);
    size_t o0 = (size_t)row * CDIM;
    out[o0 + tid]       = (v0 - mean) * rstd * g[tid]       + b[tid];
    out[o0 + tid + 128] = (v1 - mean) * rstd * g[tid + 128] + b[tid + 128];
    out[o0 + tid + 256] = (v2 - mean) * rstd * g[tid + 256] + b[tid + 256];
}

// ---------------- attention: one block per (window, head) ----------------
__global__ __launch_bounds__(128)
void attn_kernel(const float* __restrict__ qkv, const float* __restrict__ rpb,
                 const float* __restrict__ mask, float* __restrict__ out) {
    int bn = blockIdx.x;
    int h = blockIdx.y;
    __shared__ float qs[NTOK][33];
    __shared__ float ks[NTOK][33];
    __shared__ float vs[NTOK][32];
    __shared__ float sc[NTOK][50];
    int tid = threadIdx.x;

    size_t base = (size_t)bn * NTOK * QKVN + h * HDIM;
    for (int idx = tid; idx < NTOK * HDIM; idx += 128) {
        int i = idx >> 5, d = idx & 31;
        size_t o = base + (size_t)i * QKVN + d;
        qs[i][d] = qkv[o] * 0.17677669529663687f;
        ks[i][d] = qkv[o + CDIM];
        vs[i][d] = qkv[o + 2 * CDIM];
    }
    __syncthreads();

    const float* mrow = mask + (size_t)(bn & 63) * (NTOK * NTOK);
    for (int t = tid; t < NTOK * NTOK; t += 128) {
        int i = t / NTOK, j = t - (t / NTOK) * NTOK;
        float s = 0.0f;
#pragma unroll
        for (int d = 0; d < HDIM; d++) s += qs[i][d] * ks[j][d];
        int yi = i / WSZ, xi = i % WSZ, yj = j / WSZ, xj = j % WSZ;
        s += rpb[((yi - yj + 6) * 13 + (xi - xj + 6)) * NHEADS + h];
        s += mrow[t];
        sc[i][j] = s;
    }
    __syncthreads();

    if (tid < NTOK) {
        float m = -1e30f;
#pragma unroll
        for (int j = 0; j < NTOK; j++) m = fmaxf(m, sc[tid][j]);
        float sum = 0.0f;
#pragma unroll
        for (int j = 0; j < NTOK; j++) {
            float e = __expf(sc[tid][j] - m);
            sc[tid][j] = e;
            sum += e;
        }
        float inv = 1.0f / sum;
#pragma unroll
        for (int j = 0; j < NTOK; j++) sc[tid][j] *= inv;
    }
    __syncthreads();

    for (int t = tid; t < NTOK * HDIM; t += 128) {
        int i = t >> 5, d = t & 31;
        float s = 0.0f;
#pragma unroll
        for (int j = 0; j < NTOK; j++) s += sc[i][j] * vs[j][d];
        out[((size_t)bn * NTOK + i) * CDIM + h * HDIM + d] = s;
    }
}

// ---------------- launch ----------------
extern "C" void kernel_launch(void* const* d_in, const int* in_sizes, int n_in,
                              void* d_out, int out_size) {
    const float* x        = (const float*)d_in[0];
    const float* attnmask = (const float*)d_in[1];
    const float* n1g      = (const float*)d_in[2];
    const float* n1b      = (const float*)d_in[3];
    const float* qkv_w    = (const float*)d_in[4];
    const float* qkv_b    = (const float*)d_in[5];
    const float* rpb      = (const float*)d_in[6];
    const float* proj_w   = (const float*)d_in[7];
    const float* proj_b   = (const float*)d_in[8];
    const float* n2g      = (const float*)d_in[9];
    const float* n2b      = (const float*)d_in[10];
    const float* fc1_w    = (const float*)d_in[11];
    const float* fc1_b    = (const float*)d_in[12];
    const float* fc2_w    = (const float*)d_in[13];
    const float* fc2_b    = (const float*)d_in[14];
    float* out = (float*)d_out;

    float *p_win, *p_qkv, *p_att, *p_hid, *p_qkvT, *p_projT, *p_fc1T, *p_fc2T;
    cudaGetSymbolAddress((void**)&p_win, g_win);
    cudaGetSymbolAddress((void**)&p_qkv, g_qkv);
    cudaGetSymbolAddress((void**)&p_att, g_att);
    cudaGetSymbolAddress((void**)&p_hid, g_hid);
    cudaGetSymbolAddress((void**)&p_qkvT, g_qkvT);
    cudaGetSymbolAddress((void**)&p_projT, g_projT);
    cudaGetSymbolAddress((void**)&p_fc1T, g_fc1T);
    cudaGetSymbolAddress((void**)&p_fc2T, g_fc2T);

    cudaFuncSetAttribute(mma_gemm<0>, cudaFuncAttributeMaxDynamicSharedMemorySize, GSMEM_BYTES);
    cudaFuncSetAttribute(mma_gemm<1>, cudaFuncAttributeMaxDynamicSharedMemorySize, GSMEM_BYTES);
    cudaFuncSetAttribute(mma_gemm<2>, cudaFuncAttributeMaxDynamicSharedMemorySize, GSMEM_BYTES);
    cudaFuncSetAttribute(mma_gemm<3>, cudaFuncAttributeMaxDynamicSharedMemorySize, GSMEM_BYTES);

    // 0. transpose weights to [N, K]
    transpose_k<<<dim3(QKVN / 32, CDIM / 32), dim3(32, 8)>>>(qkv_w, p_qkvT, CDIM, QKVN);
    transpose_k<<<dim3(CDIM / 32, CDIM / 32), dim3(32, 8)>>>(proj_w, p_projT, CDIM, CDIM);
    transpose_k<<<dim3(HID / 32, CDIM / 32), dim3(32, 8)>>>(fc1_w, p_fc1T, CDIM, HID);
    transpose_k<<<dim3(CDIM / 32, HID / 32), dim3(32, 8)>>>(fc2_w, p_fc2T, HID, CDIM);

    // 1. LN1 + shift + window partition
    ln1_part_kernel<<<ROWS, 128>>>(x, n1g, n1b, p_win);

    // 2. QKV GEMM
    mma_gemm<0><<<dim3(QKVN / 128, ROWS / 128), 256, GSMEM_BYTES>>>(
        p_win, p_qkvT, qkv_b, p_qkv, CDIM, QKVN, nullptr);

    // 3. windowed attention
    attn_kernel<<<dim3(BN, NHEADS), 128>>>(p_qkv, rpb, attnmask, p_att);

    // 4. proj GEMM + window reverse + residual -> d_out
    mma_gemm<1><<<dim3(CDIM / 128, ROWS / 128), 256, GSMEM_BYTES>>>(
        p_att, p_projT, proj_b, out, CDIM, CDIM, x);

    // 5. LN2
    ln2_kernel<<<ROWS, 128>>>(out, n2g, n2b, p_win);

    // 6. fc1 + GELU
    mma_gemm<2><<<dim3(HID / 128, ROWS / 128), 256, GSMEM_BYTES>>>(
        p_win, p_fc1T, fc1_b, p_hid, CDIM, HID, nullptr);

    // 7. fc2 + residual accumulate into d_out
    mma_gemm<3><<<dim3(CDIM / 128, ROWS / 128), 256, GSMEM_BYTES>>>(
        p_hid, p_fc2T, fc2_b, out, HID, CDIM, nullptr);
}

// round 7
// speedup vs baseline: 3.1219x; 1.9216x over previous
#include <cuda_runtime.h>
#include <cuda_bf16.h>
#include <cstdint>
#include <math.h>

// ---------------- problem constants ----------------
#define BATCH 32
#define HH 56
#define WW 56
#define CDIM 384
#define NHEADS 12
#define HDIM 32
#define WSZ 7
#define NTOK 49
#define NWIN 64
#define BN 2048
#define ROWS 100352
#define HID 1536
#define QKVN 1152

// ---------------- scratch ----------------
__device__ float g_win[(size_t)ROWS * CDIM];
__device__ float g_qkv[(size_t)ROWS * QKVN];
__device__ float g_att[(size_t)ROWS * CDIM];
__device__ float g_hid[(size_t)ROWS * HID];
__device__ float g_qkvT[(size_t)QKVN * CDIM];
__device__ float g_projT[(size_t)CDIM * CDIM];
__device__ float g_fc1T[(size_t)HID * CDIM];
__device__ float g_fc2T[(size_t)CDIM * HID];

// ---------------- helpers ----------------
__device__ __forceinline__ uint32_t s2u(const void* p) {
    uint32_t a;
    asm("{ .reg .u64 t; cvta.to.shared.u64 t, %1; cvt.u32.u64 %0, t; }" : "=r"(a) : "l"(p));
    return a;
}
__device__ __forceinline__ void mma_tf32(float* c, const uint32_t* a, const uint32_t* b) {
    asm volatile(
        "mma.sync.aligned.m16n8k8.row.col.f32.tf32.tf32.f32 "
        "{%0,%1,%2,%3}, {%4,%5,%6,%7}, {%8,%9}, {%0,%1,%2,%3};"
        : "+f"(c[0]), "+f"(c[1]), "+f"(c[2]), "+f"(c[3])
        : "r"(a[0]), "r"(a[1]), "r"(a[2]), "r"(a[3]), "r"(b[0]), "r"(b[1]));
}
__device__ __forceinline__ void ldsm4(uint32_t* r, uint32_t addr) {
    asm volatile("ldmatrix.sync.aligned.m8n8.x4.shared.b16 {%0,%1,%2,%3}, [%4];"
                 : "=r"(r[0]), "=r"(r[1]), "=r"(r[2]), "=r"(r[3]) : "r"(addr));
}
__device__ __forceinline__ void cp16(uint32_t dst, const void* src) {
    asm volatile("cp.async.cg.shared.global [%0], [%1], 16;" :: "r"(dst), "l"(src));
}
#define CP_COMMIT() asm volatile("cp.async.commit_group;" ::: "memory")
#define CP_WAIT2()  asm volatile("cp.async.wait_group 2;" ::: "memory")

// ======================= tf32 mma.sync GEMM (cp.async + ldmatrix) =======================
// Block 128x128, 8 warps (2m x 4n), warp tile 64x32, BK=32, 3-stage cp.async pipeline.
// A: [M,K] row-major f32. Bt: [N,K] row-major f32 (== col-major B for mma).
// smem per stage: A tile 128x32 f32 (16KB) + B tile (16KB); rows of 128B, 16B chunks
// XOR-swizzled: physical_chunk = chunk ^ (row & 7).
#define STAGE_BYTES 32768
#define GSMEM_BYTES (3 * STAGE_BYTES)   // 96 KB

// EPI: 0 bias+store | 1 bias+scatter+residual | 2 bias+GELU | 3 bias+accumulate
template <int EPI>
__global__ void __launch_bounds__(256)
mma_gemm(const float* __restrict__ A, const float* __restrict__ Bt,
         const float* __restrict__ bias, float* __restrict__ C,
         int K, int Nm, const float* __restrict__ resid) {
    extern __shared__ __align__(1024) char smem[];
    const uint32_t sb = s2u(smem);

    const int tid = threadIdx.x;
    const int lane = tid & 31, wid = tid >> 5;
    const int wm = wid & 1, wn = wid >> 1;
    const int row0 = blockIdx.y * 128, col0 = blockIdx.x * 128;

    const float* Ab = A + (size_t)row0 * K;
    const float* Bb = Bt + (size_t)col0 * K;

    // loader mapping: 4 x 16B chunks of A and of B per thread per stage
    const int lr = tid >> 3;            // row for i=0 (rows advance by 32)
    const int lc = tid & 7;             // chunk 0..7

    // ldmatrix per-lane address components
    const int x7 = lane & 7;
    const int rowA = wm * 64 + ((lane >> 3) & 1) * 8 + x7;   // + mf*16
    const int cA = lane >> 4;                                 // chunk add (0/1)
    const int rowB = wn * 32 + (lane >> 4) * 8 + x7;          // + pair*16
    const int cB = (lane >> 3) & 1;

    float acc[4][4][4];
#pragma unroll
    for (int i = 0; i < 4; i++)
#pragma unroll
        for (int j = 0; j < 4; j++)
#pragma unroll
            for (int e = 0; e < 4; e++) acc[i][j][e] = 0.0f;

    const int nk = K >> 5;

    // ---- tile loader (cp.async) ----
    auto load_tile = [&](int s, int k0) {
        uint32_t As = sb + s * STAGE_BYTES;
        uint32_t Bs = As + 16384;
#pragma unroll
        for (int i = 0; i < 4; i++) {
            int r = lr + i * 32;
            uint32_t off = (uint32_t)r * 128 + ((uint32_t)(lc ^ (r & 7)) << 4);
            cp16(As + off, Ab + (size_t)r * K + k0 + lc * 4);
            cp16(Bs + off, Bb + (size_t)r * K + k0 + lc * 4);
        }
    };

    load_tile(0, 0); CP_COMMIT();
    load_tile(1, 32); CP_COMMIT();

    for (int it = 0; it < nk; ++it) {
        if (it + 2 < nk) load_tile((it + 2) % 3, (it + 2) << 5);
        CP_COMMIT();
        CP_WAIT2();
        __syncthreads();

        const uint32_t As = sb + (it % 3) * STAGE_BYTES;
        const uint32_t Bs = As + 16384;
#pragma unroll
        for (int kkp = 0; kkp < 4; kkp++) {           // k sub-chunks of 8
            uint32_t a[4][4], b[2][4];
#pragma unroll
            for (int mf = 0; mf < 4; mf++) {
                uint32_t addr = As + ((uint32_t)(rowA + mf * 16) << 7) +
                                ((uint32_t)((2 * kkp + cA) ^ x7) << 4);
                ldsm4(a[mf], addr);
            }
#pragma unroll
            for (int pr = 0; pr < 2; pr++) {
                uint32_t addr = Bs + ((uint32_t)(rowB + pr * 16) << 7) +
                                ((uint32_t)((2 * kkp + cB) ^ x7) << 4);
                ldsm4(b[pr], addr);
            }
#pragma unroll
            for (int mf = 0; mf < 4; mf++)
#pragma unroll
                for (int nf = 0; nf < 4; nf++)
                    mma_tf32(acc[mf][nf], a[mf], &b[nf >> 1][(nf & 1) * 2]);
        }
        __syncthreads();
    }

    // ---------------- epilogue ----------------
    const float is2 = 0.70710678118654752f;
#pragma unroll
    for (int mf = 0; mf < 4; mf++) {
#pragma unroll
        for (int h = 0; h < 2; h++) {
            int row = row0 + wm * 64 + mf * 16 + (lane >> 2) + h * 8;
            size_t base;
            if (EPI == 1) {
                int bn = row / NTOK, tok = row - bn * NTOK;
                int bbat = bn >> 6, w = bn & 63;
                int ii = (w >> 3) * WSZ + tok / WSZ;
                int jj = (w & 7) * WSZ + tok % WSZ;
                int hh = (ii < 53) ? ii + 3 : ii - 53;
                int ww2 = (jj < 53) ? jj + 3 : jj - 53;
                base = ((size_t)bbat * (HH * WW) + hh * WW + ww2) * CDIM;
            } else {
                base = (size_t)row * Nm;
            }
#pragma unroll
            for (int nf = 0; nf < 4; nf++) {
                int col = col0 + wn * 32 + nf * 8 + (lane & 3) * 2;
                float v0 = acc[mf][nf][h * 2 + 0] + bias[col];
                float v1 = acc[mf][nf][h * 2 + 1] + bias[col + 1];
                if (EPI == 2) {
                    v0 = 0.5f * v0 * (1.0f + erff(v0 * is2));
                    v1 = 0.5f * v1 * (1.0f + erff(v1 * is2));
                }
                size_t off = base + col;
                if (EPI == 1) {
                    float2 rr = *(const float2*)(resid + off);
                    float2 o; o.x = v0 + rr.x; o.y = v1 + rr.y;
                    *(float2*)(C + off) = o;
                } else if (EPI == 3) {
                    float2 o = *(float2*)(C + off);
                    o.x += v0; o.y += v1;
                    *(float2*)(C + off) = o;
                } else {
                    float2 o; o.x = v0; o.y = v1;
                    *(float2*)(C + off) = o;
                }
            }
        }
    }
}

// ---------------- weight transpose [K,N] -> [N,K] ----------------
__global__ void transpose_k(const float* __restrict__ W, float* __restrict__ Wt,
                            int K, int N) {
    __shared__ float t[32][33];
    int k0 = blockIdx.y * 32, n0 = blockIdx.x * 32;
    int x = threadIdx.x, y = threadIdx.y;
    for (int i = y; i < 32; i += 8) t[i][x] = W[(size_t)(k0 + i) * N + n0 + x];
    __syncthreads();
    for (int i = y; i < 32; i += 8) Wt[(size_t)(n0 + i) * K + k0 + x] = t[x][i];
}

// ---------------- LN1 + cyclic shift + window partition ----------------
__global__ void ln1_part_kernel(const float* __restrict__ x,
                                const float* __restrict__ g,
                                const float* __restrict__ b,
                                float* __restrict__ out) {
    int row = blockIdx.x;
    int tid = threadIdx.x;
    const float* xr = x + (size_t)row * CDIM;
    float v0 = xr[tid], v1 = xr[tid + 128], v2 = xr[tid + 256];
    float s = v0 + v1 + v2;
    float sq = v0 * v0 + v1 * v1 + v2 * v2;
#pragma unroll
    for (int o = 16; o; o >>= 1) {
        s += __shfl_down_sync(0xffffffffu, s, o);
        sq += __shfl_down_sync(0xffffffffu, sq, o);
    }
    __shared__ float rs[4], rq[4];
    int w = tid >> 5, l = tid & 31;
    if (l == 0) { rs[w] = s; rq[w] = sq; }
    __syncthreads();
    float ts = rs[0] + rs[1] + rs[2] + rs[3];
    float tq = rq[0] + rq[1] + rq[2] + rq[3];
    float mean = ts * (1.0f / CDIM);
    float var = tq * (1.0f / CDIM) - mean * mean;
    float rstd = rsqrtf(var + 1e-5f);

    int bb = row / (HH * WW);
    int rem = row - bb * (HH * WW);
    int hh = rem / WW, ww = rem - (rem / WW) * WW;
    int i = (hh >= 3) ? hh - 3 : hh + 53;
    int j = (ww >= 3) ? ww - 3 : ww + 53;
    int widx = (i / WSZ) * 8 + (j / WSZ);
    int tok = (i % WSZ) * WSZ + (j % WSZ);
    size_t drow = ((size_t)(bb * NWIN + widx) * NTOK + tok) * CDIM;
    out[drow + tid]       = (v0 - mean) * rstd * g[tid]       + b[tid];
    out[drow + tid + 128] = (v1 - mean) * rstd * g[tid + 128] + b[tid + 128];
    out[drow + tid + 256] = (v2 - mean) * rstd * g[tid + 256] + b[tid + 256];
}

// ---------------- LN2 ----------------
__global__ void ln2_kernel(const float* __restrict__ x,
                           const float* __restrict__ g,
                           const float* __restrict__ b,
                           float* __restrict__ out) {
    int row = blockIdx.x;
    int tid = threadIdx.x;
    const float* xr = x + (size_t)row * CDIM;
    float v0 = xr[tid], v1 = xr[tid + 128], v2 = xr[tid + 256];
    float s = v0 + v1 + v2;
    float sq = v0 * v0 + v1 * v1 + v2 * v2;
#pragma unroll
    for (int o = 16; o; o >>= 1) {
        s += __shfl_down_sync(0xffffffffu, s, o);
        sq += __shfl_down_sync(0xffffffffu, sq, o);
    }
    __shared__ float rs[4], rq[4];
    int w = tid >> 5, l = tid & 31;
    if (l == 0) { rs[w] = s; rq[w] = sq; }
    __syncthreads();
    float ts = rs[0] + rs[1] + rs[2] + rs[3];
    float tq = rq[0] + rq[1] + rq[2] + rq[3];
    float mean = ts * (1.0f / CDIM);
    float var = tq * (1.0f / CDIM) - mean * mean;
    float rstd = rsqrtf(var + 1e-5f);
    size_t o0 = (size_t)row * CDIM;
    out[o0 + tid]       = (v0 - mean) * rstd * g[tid]       + b[tid];
    out[o0 + tid + 128] = (v1 - mean) * rstd * g[tid + 128] + b[tid + 128];
    out[o0 + tid + 256] = (v2 - mean) * rstd * g[tid + 256] + b[tid + 256];
}

// ---------------- attention: one block per (window, head) ----------------
__global__ __launch_bounds__(128)
void attn_kernel(const float* __restrict__ qkv, const float* __restrict__ rpb,
                 const float* __restrict__ mask, float* __restrict__ out) {
    int bn = blockIdx.x;
    int h = blockIdx.y;
    __shared__ float qs[NTOK][33];
    __shared__ float ks[NTOK][33];
    __shared__ float vs[NTOK][32];
    __shared__ float sc[NTOK][50];
    int tid = threadIdx.x;

    size_t base = (size_t)bn * NTOK * QKVN + h * HDIM;
    for (int idx = tid; idx < NTOK * HDIM; idx += 128) {
        int i = idx >> 5, d = idx & 31;
        size_t o = base + (size_t)i * QKVN + d;
        qs[i][d] = qkv[o] * 0.17677669529663687f;
        ks[i][d] = qkv[o + CDIM];
        vs[i][d] = qkv[o + 2 * CDIM];
    }
    __syncthreads();

    const float* mrow = mask + (size_t)(bn & 63) * (NTOK * NTOK);
    for (int t = tid; t < NTOK * NTOK; t += 128) {
        int i = t / NTOK, j = t - (t / NTOK) * NTOK;
        float s = 0.0f;
#pragma unroll
        for (int d = 0; d < HDIM; d++) s += qs[i][d] * ks[j][d];
        int yi = i / WSZ, xi = i % WSZ, yj = j / WSZ, xj = j % WSZ;
        s += rpb[((yi - yj + 6) * 13 + (xi - xj + 6)) * NHEADS + h];
        s += mrow[t];
        sc[i][j] = s;
    }
    __syncthreads();

    if (tid < NTOK) {
        float m = -1e30f;
#pragma unroll
        for (int j = 0; j < NTOK; j++) m = fmaxf(m, sc[tid][j]);
        float sum = 0.0f;
#pragma unroll
        for (int j = 0; j < NTOK; j++) {
            float e = __expf(sc[tid][j] - m);
            sc[tid][j] = e;
            sum += e;
        }
        float inv = 1.0f / sum;
#pragma unroll
        for (int j = 0; j < NTOK; j++) sc[tid][j] *= inv;
    }
    __syncthreads();

    for (int t = tid; t < NTOK * HDIM; t += 128) {
        int i = t >> 5, d = t & 31;
        float s = 0.0f;
#pragma unroll
        for (int j = 0; j < NTOK; j++) s += sc[i][j] * vs[j][d];
        out[((size_t)bn * NTOK + i) * CDIM + h * HDIM + d] = s;
    }
}

// ---------------- launch ----------------
extern "C" void kernel_launch(void* const* d_in, const int* in_sizes, int n_in,
                              void* d_out, int out_size) {
    const float* x        = (const float*)d_in[0];
    const float* attnmask = (const float*)d_in[1];
    const float* n1g      = (const float*)d_in[2];
    const float* n1b      = (const float*)d_in[3];
    const float* qkv_w    = (const float*)d_in[4];
    const float* qkv_b    = (const float*)d_in[5];
    const float* rpb      = (const float*)d_in[6];
    const float* proj_w   = (const float*)d_in[7];
    const float* proj_b   = (const float*)d_in[8];
    const float* n2g      = (const float*)d_in[9];
    const float* n2b      = (const float*)d_in[10];
    const float* fc1_w    = (const float*)d_in[11];
    const float* fc1_b    = (const float*)d_in[12];
    const float* fc2_w    = (const float*)d_in[13];
    const float* fc2_b    = (const float*)d_in[14];
    float* out = (float*)d_out;

    float *p_win, *p_qkv, *p_att, *p_hid, *p_qkvT, *p_projT, *p_fc1T, *p_fc2T;
    cudaGetSymbolAddress((void**)&p_win, g_win);
    cudaGetSymbolAddress((void**)&p_qkv, g_qkv);
    cudaGetSymbolAddress((void**)&p_att, g_att);
    cudaGetSymbolAddress((void**)&p_hid, g_hid);
    cudaGetSymbolAddress((void**)&p_qkvT, g_qkvT);
    cudaGetSymbolAddress((void**)&p_projT, g_projT);
    cudaGetSymbolAddress((void**)&p_fc1T, g_fc1T);
    cudaGetSymbolAddress((void**)&p_fc2T, g_fc2T);

    cudaFuncSetAttribute(mma_gemm<0>, cudaFuncAttributeMaxDynamicSharedMemorySize, GSMEM_BYTES);
    cudaFuncSetAttribute(mma_gemm<1>, cudaFuncAttributeMaxDynamicSharedMemorySize, GSMEM_BYTES);
    cudaFuncSetAttribute(mma_gemm<2>, cudaFuncAttributeMaxDynamicSharedMemorySize, GSMEM_BYTES);
    cudaFuncSetAttribute(mma_gemm<3>, cudaFuncAttributeMaxDynamicSharedMemorySize, GSMEM_BYTES);

    // 0. transpose weights to [N, K]
    transpose_k<<<dim3(QKVN / 32, CDIM / 32), dim3(32, 8)>>>(qkv_w, p_qkvT, CDIM, QKVN);
    transpose_k<<<dim3(CDIM / 32, CDIM / 32), dim3(32, 8)>>>(proj_w, p_projT, CDIM, CDIM);
    transpose_k<<<dim3(HID / 32, CDIM / 32), dim3(32, 8)>>>(fc1_w, p_fc1T, CDIM, HID);
    transpose_k<<<dim3(CDIM / 32, HID / 32), dim3(32, 8)>>>(fc2_w, p_fc2T, HID, CDIM);

    // 1. LN1 + shift + window partition
    ln1_part_kernel<<<ROWS, 128>>>(x, n1g, n1b, p_win);

    // 2. QKV GEMM
    mma_gemm<0><<<dim3(QKVN / 128, ROWS / 128), 256, GSMEM_BYTES>>>(
        p_win, p_qkvT, qkv_b, p_qkv, CDIM, QKVN, nullptr);

    // 3. windowed attention
    attn_kernel<<<dim3(BN, NHEADS), 128>>>(p_qkv, rpb, attnmask, p_att);

    // 4. proj GEMM + window reverse + residual -> d_out
    mma_gemm<1><<<dim3(CDIM / 128, ROWS / 128), 256, GSMEM_BYTES>>>(
        p_att, p_projT, proj_b, out, CDIM, CDIM, x);

    // 5. LN2
    ln2_kernel<<<ROWS, 128>>>(out, n2g, n2b, p_win);

    // 6. fc1 + GELU
    mma_gemm<2><<<dim3(HID / 128, ROWS / 128), 256, GSMEM_BYTES>>>(
        p_win, p_fc1T, fc1_b, p_hid, CDIM, HID, nullptr);

    // 7. fc2 + residual accumulate into d_out
    mma_gemm<3><<<dim3(CDIM / 128, ROWS / 128), 256, GSMEM_BYTES>>>(
        p_hid, p_fc2T, fc2_b, out, HID, CDIM, nullptr);
}